// round 1
// baseline (speedup 1.0000x reference)
#include <cuda_runtime.h>
#include <math.h>

// ---------------------------------------------------------------------------
// LSTM: B=128, T=512, D=256, H=1024, C=10
// Phase 1: xp[t][b][4H] = x@[Wgx|Wix|Wfx|Wox] + bias      (parallel, 137 GFLOP)
// Phase 2: 512 sequential steps: z = xp[t] + h@Wh ; gates  (serial, 550 GFLOP)
// Phase 3: out = h_T @ W_ph + b_p                          (tiny)
// All fp32 (baseline for exact correctness).
// ---------------------------------------------------------------------------

namespace {
constexpr int T_  = 512;
constexpr int B_  = 128;
constexpr int D_  = 256;
constexpr int H_  = 1024;
constexpr int C_  = 10;
constexpr int G4_ = 4 * H_;   // 4096
}

struct Ptrs4 { const float* p[4]; };

// Scratch (device globals; allocation-free per harness rules)
__device__ float g_xp[(size_t)T_ * B_ * G4_];   // 1 GiB
__device__ float g_h[2][B_ * H_];
__device__ float g_c[B_ * H_];

// ---------------------------------------------------------------------------
__global__ void init_state() {
    int i = blockIdx.x * blockDim.x + threadIdx.x;
    if (i < B_ * H_) { g_h[0][i] = 0.f; g_c[i] = 0.f; }
}

// ---------------------------------------------------------------------------
// Phase 1: xp GEMM. M = T*B = 65536 (row m -> t = m>>7, b = m&127),
// K = 256, N = 1024 per gate (blockIdx.z = gate).
// Tile 128x64, BK=16, 256 threads, 8x4 per thread.
// ---------------------------------------------------------------------------
__global__ void xp_gemm(const float* __restrict__ x, Ptrs4 W, Ptrs4 bias) {
    constexpr int BM = 128, BN = 64, BK = 16;
    __shared__ float As[BK][BM];
    __shared__ float Bs[BK][BN];

    const int gate = blockIdx.z;
    const float* __restrict__ Wg = W.p[gate];
    const float* __restrict__ bg = bias.p[gate];
    const int n0 = blockIdx.x * BN;
    const int m0 = blockIdx.y * BM;
    const int tid = threadIdx.x;
    const int tx = tid & 15;       // column group (4 cols)
    const int ty = tid >> 4;       // row group (8 rows)

    float acc[8][4];
    #pragma unroll
    for (int i = 0; i < 8; i++)
        #pragma unroll
        for (int j = 0; j < 4; j++) acc[i][j] = 0.f;

    // A-load mapping: thread loads 8 consecutive k of one row
    const int lr = tid >> 1;             // 0..127
    const int lk = (tid & 1) * 8;        // 0 or 8
    const int m  = m0 + lr;
    const int t_idx = m >> 7;
    const int b_idx = m & 127;
    const float* __restrict__ xrow = x + ((size_t)b_idx * T_ + t_idx) * D_;

    // B-load mapping: 16 threads per k-row, 4 consecutive cols each
    const int br = tid >> 4;             // 0..15
    const int bc = (tid & 15) * 4;

    for (int k0 = 0; k0 < D_; k0 += BK) {
        float4 a0 = *(const float4*)(xrow + k0 + lk);
        float4 a1 = *(const float4*)(xrow + k0 + lk + 4);
        float4 b0 = *(const float4*)(Wg + (size_t)(k0 + br) * H_ + n0 + bc);
        As[lk + 0][lr] = a0.x; As[lk + 1][lr] = a0.y;
        As[lk + 2][lr] = a0.z; As[lk + 3][lr] = a0.w;
        As[lk + 4][lr] = a1.x; As[lk + 5][lr] = a1.y;
        As[lk + 6][lr] = a1.z; As[lk + 7][lr] = a1.w;
        *(float4*)&Bs[br][bc] = b0;
        __syncthreads();

        #pragma unroll
        for (int kk = 0; kk < BK; kk++) {
            float4 av0 = *(const float4*)&As[kk][ty * 8];
            float4 av1 = *(const float4*)&As[kk][ty * 8 + 4];
            float4 bv  = *(const float4*)&Bs[kk][tx * 4];
            float a[8] = {av0.x, av0.y, av0.z, av0.w, av1.x, av1.y, av1.z, av1.w};
            float b[4] = {bv.x, bv.y, bv.z, bv.w};
            #pragma unroll
            for (int i = 0; i < 8; i++)
                #pragma unroll
                for (int j = 0; j < 4; j++)
                    acc[i][j] += a[i] * b[j];
        }
        __syncthreads();
    }

    float4 bvv = *(const float4*)(bg + n0 + tx * 4);
    #pragma unroll
    for (int i = 0; i < 8; i++) {
        int mrow = m0 + ty * 8 + i;
        float* dst = g_xp + (size_t)mrow * G4_ + gate * H_ + n0 + tx * 4;
        float4 v;
        v.x = acc[i][0] + bvv.x; v.y = acc[i][1] + bvv.y;
        v.z = acc[i][2] + bvv.z; v.w = acc[i][3] + bvv.w;
        *(float4*)dst = v;
    }
}

// ---------------------------------------------------------------------------
// Phase 2: one LSTM step. z(128 x 4H) = xp[t] + h @ Wh, fused gate epilogue.
// Each block owns BNH=8 hidden units across ALL 4 gates (32 z-columns),
// so the gate fusion + c/h update happens entirely in-block.
// 128 blocks x 256 threads. Per thread: 4 rows x 4 gates. BK=32.
// ---------------------------------------------------------------------------
__global__ void lstm_step(int t, Ptrs4 Wh) {
    constexpr int BK = 32, BNH = 8;
    __shared__ float Hs[BK][B_];          // 16 KB
    __shared__ float Ws[BK][4 * BNH];     // 4 KB   (col = gate*8 + jj)

    const float* __restrict__ hin  = g_h[t & 1];
    float*       __restrict__ hout = g_h[(t + 1) & 1];
    const float* __restrict__ xp_t = g_xp + (size_t)t * B_ * G4_;

    const int J0  = blockIdx.x * BNH;
    const int tid = threadIdx.x;
    const int jj  = tid & 7;      // hidden unit within block
    const int rg  = tid >> 3;     // row group (4 rows), 0..31

    float acc[4][4];              // [row][gate]
    #pragma unroll
    for (int i = 0; i < 4; i++)
        #pragma unroll
        for (int g = 0; g < 4; g++) acc[i][g] = 0.f;

    // H-load mapping: thread loads 16 consecutive k of one row
    const int lr = tid >> 1;             // 0..127
    const int lk = (tid & 1) * 16;       // 0 or 16
    // W-load mapping: 4 consecutive packed cols of one k-row
    const int wkk = tid >> 3;            // 0..31
    const int wcc = (tid & 7) * 4;       // 0,4,...,28  == gate*8 + j0
    const int wg  = wcc >> 3;
    const int wj  = wcc & 7;
    const float* __restrict__ Wsrc = Wh.p[wg];

    for (int k0 = 0; k0 < H_; k0 += BK) {
        #pragma unroll
        for (int q = 0; q < 4; q++) {
            float4 v = *(const float4*)(hin + (size_t)lr * H_ + k0 + lk + q * 4);
            Hs[lk + q * 4 + 0][lr] = v.x;
            Hs[lk + q * 4 + 1][lr] = v.y;
            Hs[lk + q * 4 + 2][lr] = v.z;
            Hs[lk + q * 4 + 3][lr] = v.w;
        }
        float4 wv = *(const float4*)(Wsrc + (size_t)(k0 + wkk) * H_ + J0 + wj);
        *(float4*)&Ws[wkk][wcc] = wv;
        __syncthreads();

        #pragma unroll
        for (int kk = 0; kk < BK; kk++) {
            float4 av = *(const float4*)&Hs[kk][rg * 4];
            float a[4] = {av.x, av.y, av.z, av.w};
            float bv[4];
            #pragma unroll
            for (int g = 0; g < 4; g++) bv[g] = Ws[kk][g * 8 + jj];
            #pragma unroll
            for (int i = 0; i < 4; i++)
                #pragma unroll
                for (int g = 0; g < 4; g++)
                    acc[i][g] += a[i] * bv[g];
        }
        __syncthreads();
    }

    const int J = J0 + jj;
    #pragma unroll
    for (int i = 0; i < 4; i++) {
        const int brow = rg * 4 + i;
        const size_t idx = (size_t)brow * H_ + J;
        const float* __restrict__ xr = xp_t + (size_t)brow * G4_;
        float zg = acc[i][0] + xr[0 * H_ + J];
        float zi = acc[i][1] + xr[1 * H_ + J];
        float zf = acc[i][2] + xr[2 * H_ + J];
        float zo = acc[i][3] + xr[3 * H_ + J];
        float gv = tanhf(zg);
        float iv = 1.f / (1.f + expf(-zi));
        float fv = 1.f / (1.f + expf(-zf));
        float ov = 1.f / (1.f + expf(-zo));
        float cn = gv * iv + g_c[idx] * fv;
        g_c[idx]  = cn;
        hout[idx] = tanhf(cn) * ov;
    }
}

// ---------------------------------------------------------------------------
// Phase 3: out[b][c] = h_T[b] @ W_ph + b_p  (128 x 10, K=1024)
// h_T lives in g_h[0] after 512 steps (t=511 writes buffer (511+1)&1 = 0).
// ---------------------------------------------------------------------------
__global__ void proj_kernel(const float* __restrict__ Wp,
                            const float* __restrict__ bp,
                            float* __restrict__ out) {
    const int b   = blockIdx.x;
    const int tid = threadIdx.x;
    const float* __restrict__ h = g_h[0] + (size_t)b * H_;

    float acc[C_];
    #pragma unroll
    for (int cc = 0; cc < C_; cc++) acc[cc] = 0.f;
    for (int j = tid; j < H_; j += blockDim.x) {
        float hv = h[j];
        #pragma unroll
        for (int cc = 0; cc < C_; cc++) acc[cc] += hv * Wp[(size_t)j * C_ + cc];
    }

    __shared__ float red[256];
    for (int cc = 0; cc < C_; cc++) {
        red[tid] = acc[cc];
        __syncthreads();
        for (int s = 128; s > 0; s >>= 1) {
            if (tid < s) red[tid] += red[tid + s];
            __syncthreads();
        }
        if (tid == 0) out[(size_t)b * C_ + cc] = red[0] + bp[cc];
        __syncthreads();
    }
}

// ---------------------------------------------------------------------------
extern "C" void kernel_launch(void* const* d_in, const int* in_sizes, int n_in,
                              void* d_out, int out_size) {
    // Identify inputs by element count (robust to metadata ordering; gate
    // order g,i,f,o is preserved within each size class either way).
    const float* x = nullptr;
    Ptrs4 Wx{}; Ptrs4 Wh{}; Ptrs4 bb{};
    const float* Wp = nullptr;
    const float* bp = nullptr;
    int nx = 0, nh = 0, nb = 0;
    for (int i = 0; i < n_in; i++) {
        const int sz = in_sizes[i];
        const float* p = (const float*)d_in[i];
        if      (sz == B_ * T_ * D_) x = p;
        else if (sz == D_ * H_)      { if (nx < 4) Wx.p[nx++] = p; }
        else if (sz == H_ * H_)      { if (nh < 4) Wh.p[nh++] = p; }
        else if (sz == H_)           { if (nb < 4) bb.p[nb++] = p; }
        else if (sz == H_ * C_)      Wp = p;
        else if (sz == C_)           bp = p;
    }

    init_state<<<(B_ * H_ + 255) / 256, 256>>>();
    xp_gemm<<<dim3(H_ / 64, (T_ * B_) / 128, 4), 256>>>(x, Wx, bb);
    for (int t = 0; t < T_; t++)
        lstm_step<<<H_ / 8, 256>>>(t, Wh);
    proj_kernel<<<B_, 256>>>(Wp, bp, (float*)d_out);
}

// round 5
// speedup vs baseline: 2.8721x; 2.8721x over previous
#include <cuda_runtime.h>
#include <cuda_bf16.h>
#include <math.h>
#include <stdint.h>

// ---------------------------------------------------------------------------
// LSTM: B=128, T=512, D=256, H=1024, C=10  (sm_100-safe tensor cores:
// mma.sync.m16n8k16 bf16, hi/lo split x3 for near-fp32 precision)
//
// Packed gate layout p = (j>>3)*32 + g*8 + (j&7)  (j = hidden unit, g = gate)
//   -> each MMA thread fragment holds all 4 gates of the same (row, j).
// Phase 1: xp[t][b][p] = x @ Wx_packed + bias   (bf16-split MMA)
// Phase 2: 512 steps: z = xp[t] + h @ Wh_packed (bf16-split MMA, fused gates)
// Phase 3: out = h_T @ W_ph + b_p
// ---------------------------------------------------------------------------

namespace {
constexpr int T_  = 512;
constexpr int B_  = 128;
constexpr int D_  = 256;
constexpr int H_  = 1024;
constexpr int C_  = 10;
constexpr int G4_ = 4 * H_;   // 4096

// step kernel smem layout (bytes), LDA=144 (64 bf16 + pad), LDB=80 (32 bf16 + pad)
constexpr int S_ALO  = 18432;              // 128*144
constexpr int S_BHI  = 36864;
constexpr int S_BLO  = 41984;              // +64*80
constexpr int S_BUF  = 47104;
constexpr int S_SMEM = 2 * S_BUF;          // 94208, double buffered

// xp kernel smem (single buffer), LDA=144, LDB=144 (64 bf16 + pad)
constexpr int X_ALO  = 18432;
constexpr int X_BHI  = 36864;
constexpr int X_BLO  = 46080;              // +64*144
constexpr int X_SMEM = 55296;
}

struct Ptrs4 { const float* p[4]; };

// Device-global scratch (allocation-free rules)
__device__ float          g_xp[(size_t)T_ * B_ * G4_];     // 1 GiB, packed-p layout
__device__ __nv_bfloat16  g_Wb_hi[(size_t)H_ * G4_];       // Wh packed [k][p]
__device__ __nv_bfloat16  g_Wb_lo[(size_t)H_ * G4_];
__device__ __nv_bfloat16  g_Wxb_hi[(size_t)D_ * G4_];      // Wx packed [k][p]
__device__ __nv_bfloat16  g_Wxb_lo[(size_t)D_ * G4_];
__device__ float          g_bias[G4_];                     // packed bias
__device__ __nv_bfloat16  g_h_hi[2][B_ * H_];
__device__ __nv_bfloat16  g_h_lo[2][B_ * H_];
__device__ float          g_c[B_ * H_];

// ------------------------------- helpers -----------------------------------
__device__ __forceinline__ uint32_t smem_u32(const void* p) {
    uint32_t a;
    asm("{ .reg .u64 t; cvta.to.shared.u64 t, %1; cvt.u32.u64 %0, t; }"
        : "=r"(a) : "l"(p));
    return a;
}
__device__ __forceinline__ void ldsm4(uint32_t* r, uint32_t a) {
    asm volatile("ldmatrix.sync.aligned.m8n8.x4.shared.b16 {%0,%1,%2,%3}, [%4];"
                 : "=r"(r[0]), "=r"(r[1]), "=r"(r[2]), "=r"(r[3]) : "r"(a));
}
__device__ __forceinline__ void ldsm4t(uint32_t* r, uint32_t a) {
    asm volatile("ldmatrix.sync.aligned.m8n8.x4.trans.shared.b16 {%0,%1,%2,%3}, [%4];"
                 : "=r"(r[0]), "=r"(r[1]), "=r"(r[2]), "=r"(r[3]) : "r"(a));
}
__device__ __forceinline__ void mma16816(float* c, const uint32_t* a, const uint32_t* b) {
    asm volatile("mma.sync.aligned.m16n8k16.row.col.f32.bf16.bf16.f32 "
                 "{%0,%1,%2,%3}, {%4,%5,%6,%7}, {%8,%9}, {%0,%1,%2,%3};"
                 : "+f"(c[0]), "+f"(c[1]), "+f"(c[2]), "+f"(c[3])
                 : "r"(a[0]), "r"(a[1]), "r"(a[2]), "r"(a[3]), "r"(b[0]), "r"(b[1]));
}
#define CPA16(dst, src) \
    asm volatile("cp.async.cg.shared.global [%0], [%1], 16;" :: "r"(dst), "l"(src))
#define CPA_COMMIT() asm volatile("cp.async.commit_group;" ::: "memory")
#define CPA_WAIT0()  asm volatile("cp.async.wait_group 0;" ::: "memory")
#define CPA_WAIT1()  asm volatile("cp.async.wait_group 1;" ::: "memory")

__device__ __forceinline__ float sigf(float z) {
    return __fdividef(1.f, 1.f + __expf(-z));
}
__device__ __forceinline__ float tanh_fast(float z) {
    return 2.f * __fdividef(1.f, 1.f + __expf(-2.f * z)) - 1.f;
}

// ---------------------------------------------------------------------------
__global__ void init_state() {
    int i = blockIdx.x * blockDim.x + threadIdx.x;
    if (i < B_ * H_) {
        g_h_hi[0][i] = __float2bfloat16(0.f);
        g_h_lo[0][i] = __float2bfloat16(0.f);
        g_c[i] = 0.f;
    }
}

// Repack W[g][k][j] fp32 -> bf16 hi/lo at [k][p], p = (j>>3)*32 + g*8 + (j&7)
__global__ void repack_wh(Ptrs4 Wh) {
    const int k = blockIdx.x;
    for (int g = 0; g < 4; g++) {
        const float* __restrict__ src = Wh.p[g] + (size_t)k * H_;
        for (int j = threadIdx.x; j < H_; j += 256) {
            float w = src[j];
            int p = ((j >> 3) << 5) + (g << 3) + (j & 7);
            __nv_bfloat16 hi = __float2bfloat16(w);
            g_Wb_hi[(size_t)k * G4_ + p] = hi;
            g_Wb_lo[(size_t)k * G4_ + p] = __float2bfloat16(w - __bfloat162float(hi));
        }
    }
}
__global__ void repack_wx(Ptrs4 Wx) {
    const int k = blockIdx.x;
    for (int g = 0; g < 4; g++) {
        const float* __restrict__ src = Wx.p[g] + (size_t)k * H_;
        for (int j = threadIdx.x; j < H_; j += 256) {
            float w = src[j];
            int p = ((j >> 3) << 5) + (g << 3) + (j & 7);
            __nv_bfloat16 hi = __float2bfloat16(w);
            g_Wxb_hi[(size_t)k * G4_ + p] = hi;
            g_Wxb_lo[(size_t)k * G4_ + p] = __float2bfloat16(w - __bfloat162float(hi));
        }
    }
}
__global__ void repack_bias(Ptrs4 bb) {
    int p = blockIdx.x * blockDim.x + threadIdx.x;
    if (p < G4_) {
        int g = (p >> 3) & 3;
        int j = ((p >> 5) << 3) | (p & 7);
        g_bias[p] = bb.p[g][j];
    }
}

// ---------------------------------------------------------------------------
// Phase 1: xp MMA. grid (nb=64, t=512). CTA: rows b 0..127, cols p in
// [nb*64, nb*64+64), K=256 in 4 chunks of 64. Warp w: rows w*16..+16, all 64 n.
// ---------------------------------------------------------------------------
__global__ void __launch_bounds__(256, 1) xp_mma(const float* __restrict__ x) {
    extern __shared__ __align__(128) char sm[];
    const uint32_t smb = smem_u32(sm);
    const int nb = blockIdx.x, t = blockIdx.y;
    const int tid = threadIdx.x, w = tid >> 5, lane = tid & 31;

    float acc[8][4];
    #pragma unroll
    for (int f = 0; f < 8; f++)
        #pragma unroll
        for (int q = 0; q < 4; q++) acc[f][q] = 0.f;

    const uint32_t aH = smb + (w * 16 + (lane & 15)) * 144 + (lane >> 4) * 16;
    const uint32_t aL = aH + X_ALO;
    const uint32_t bH = smb + X_BHI + (lane & 15) * 144 + (lane >> 4) * 16;
    const uint32_t bL = bH + (X_BLO - X_BHI);

    for (int c = 0; c < 4; c++) {
        const int kb = c * 64;
        // B tiles via cp.async: 64 k-rows x 64 cols, hi+lo
        #pragma unroll
        for (int s = 0; s < 2; s++) {
            int i = tid + s * 256;            // 0..511
            int row = i >> 3, seg = i & 7;
            uint32_t d = smb + X_BHI + row * 144 + seg * 16;
            size_t go = (size_t)(kb + row) * G4_ + nb * 64 + seg * 8;
            CPA16(d, g_Wxb_hi + go);
            CPA16(d + (X_BLO - X_BHI), g_Wxb_lo + go);
        }
        CPA_COMMIT();
        // A: load x fp32, split hi/lo, store to smem
        #pragma unroll
        for (int s = 0; s < 8; s++) {
            int i = tid + s * 256;            // 0..2047 quads
            int row = i >> 4, q = i & 15;
            float4 v = *(const float4*)(x + ((size_t)row * T_ + t) * D_ + kb + q * 4);
            __nv_bfloat16 h0 = __float2bfloat16(v.x), h1 = __float2bfloat16(v.y);
            __nv_bfloat16 h2 = __float2bfloat16(v.z), h3 = __float2bfloat16(v.w);
            __nv_bfloat162 p0(h0, h1), p1(h2, h3);
            __nv_bfloat162 l0(__float2bfloat16(v.x - __bfloat162float(h0)),
                              __float2bfloat16(v.y - __bfloat162float(h1)));
            __nv_bfloat162 l1(__float2bfloat16(v.z - __bfloat162float(h2)),
                              __float2bfloat16(v.w - __bfloat162float(h3)));
            char* base = sm + row * 144 + q * 8;
            *(__nv_bfloat162*)(base)              = p0;
            *(__nv_bfloat162*)(base + 4)          = p1;
            *(__nv_bfloat162*)(base + X_ALO)      = l0;
            *(__nv_bfloat162*)(base + X_ALO + 4)  = l1;
        }
        CPA_WAIT0();
        __syncthreads();

        #pragma unroll
        for (int kk = 0; kk < 64; kk += 16) {
            uint32_t ah[4], al[4], bh[4][4], bl[4][4];
            ldsm4(ah, aH + kk * 2);
            ldsm4(al, aL + kk * 2);
            #pragma unroll
            for (int nb4 = 0; nb4 < 4; nb4++) {
                ldsm4t(bh[nb4], bH + kk * 144 + nb4 * 32);
                ldsm4t(bl[nb4], bL + kk * 144 + nb4 * 32);
            }
            #pragma unroll
            for (int nb4 = 0; nb4 < 4; nb4++) {
                mma16816(acc[nb4 * 2],     ah, bh[nb4]);
                mma16816(acc[nb4 * 2 + 1], ah, bh[nb4] + 2);
                mma16816(acc[nb4 * 2],     ah, bl[nb4]);
                mma16816(acc[nb4 * 2 + 1], ah, bl[nb4] + 2);
                mma16816(acc[nb4 * 2],     al, bh[nb4]);
                mma16816(acc[nb4 * 2 + 1], al, bh[nb4] + 2);
            }
        }
        __syncthreads();
    }

    // epilogue: write packed xp (+bias)
    const int r0 = w * 16 + (lane >> 2), r1 = r0 + 8;
    const int jm = (lane & 3) * 2;
    #pragma unroll
    for (int f = 0; f < 8; f++) {
        int p = nb * 64 + f * 8 + jm;
        float2 bv = *(const float2*)(g_bias + p);
        float2 v0, v1;
        v0.x = acc[f][0] + bv.x; v0.y = acc[f][1] + bv.y;
        v1.x = acc[f][2] + bv.x; v1.y = acc[f][3] + bv.y;
        *(float2*)(g_xp + ((size_t)t * B_ + r0) * G4_ + p) = v0;
        *(float2*)(g_xp + ((size_t)t * B_ + r1) * G4_ + p) = v1;
    }
}

// ---------------------------------------------------------------------------
// Phase 2: LSTM step. 128 CTAs x 256 thr. CTA ct: hidden units [8ct, 8ct+8),
// z cols p in [32ct, 32ct+32). K=1024 in 16 chunks, double-buffered cp.async.
// Warp w: rows w*16..+16, all 32 cols. Fused gate epilogue (register-local).
// ---------------------------------------------------------------------------
__global__ void __launch_bounds__(256, 1) lstm_step_mma(int t) {
    extern __shared__ __align__(128) char sm[];
    const uint32_t smb = smem_u32(sm);
    const int ct = blockIdx.x;
    const int tid = threadIdx.x, w = tid >> 5, lane = tid & 31;

    const __nv_bfloat16* __restrict__ hh = g_h_hi[t & 1];
    const __nv_bfloat16* __restrict__ hl = g_h_lo[t & 1];

    float acc[4][4];
    #pragma unroll
    for (int g = 0; g < 4; g++)
        #pragma unroll
        for (int q = 0; q < 4; q++) acc[g][q] = 0.f;

    auto issue = [&](int c) {
        const uint32_t bb = smb + (c & 1) * S_BUF;
        const int kb = c * 64;
        #pragma unroll
        for (int s = 0; s < 4; s++) {
            int i = tid + s * 256;            // 0..1023
            int row = i >> 3, seg = i & 7;
            uint32_t d = bb + row * 144 + seg * 16;
            size_t go = (size_t)row * H_ + kb + seg * 8;
            CPA16(d, hh + go);
            CPA16(d + S_ALO, hl + go);
        }
        {
            int row = tid >> 2, seg = tid & 3;  // 64 rows x 4 segs
            uint32_t d = bb + S_BHI + row * 80 + seg * 16;
            size_t go = (size_t)(kb + row) * G4_ + ct * 32 + seg * 8;
            CPA16(d, g_Wb_hi + go);
            CPA16(d + (S_BLO - S_BHI), g_Wb_lo + go);
        }
        CPA_COMMIT();
    };

    issue(0);
    for (int c = 0; c < 16; c++) {
        if (c < 15) { issue(c + 1); CPA_WAIT1(); }
        else        { CPA_WAIT0(); }
        __syncthreads();

        const uint32_t bb = smb + (c & 1) * S_BUF;
        const uint32_t aH = bb + (w * 16 + (lane & 15)) * 144 + (lane >> 4) * 16;
        const uint32_t aL = aH + S_ALO;
        const uint32_t bH = bb + S_BHI + (lane & 15) * 80 + (lane >> 4) * 16;
        const uint32_t bL = bH + (S_BLO - S_BHI);

        #pragma unroll
        for (int kk = 0; kk < 64; kk += 16) {
            uint32_t ah[4], al[4], b0h[4], b1h[4], b0l[4], b1l[4];
            ldsm4(ah, aH + kk * 2);
            ldsm4(al, aL + kk * 2);
            ldsm4t(b0h, bH + kk * 80);
            ldsm4t(b1h, bH + kk * 80 + 32);
            ldsm4t(b0l, bL + kk * 80);
            ldsm4t(b1l, bL + kk * 80 + 32);
            mma16816(acc[0], ah, b0h);     mma16816(acc[1], ah, b0h + 2);
            mma16816(acc[2], ah, b1h);     mma16816(acc[3], ah, b1h + 2);
            mma16816(acc[0], ah, b0l);     mma16816(acc[1], ah, b0l + 2);
            mma16816(acc[2], ah, b1l);     mma16816(acc[3], ah, b1l + 2);
            mma16816(acc[0], al, b0h);     mma16816(acc[1], al, b0h + 2);
            mma16816(acc[2], al, b1h);     mma16816(acc[3], al, b1h + 2);
        }
        __syncthreads();
    }

    // Fused gate epilogue. acc[g][0]=(r0,jm) [1]=(r0,jm+1) [2]=(r1,jm) [3]=(r1,jm+1)
    const int r0 = w * 16 + (lane >> 2), r1 = r0 + 8;
    const int jm = (lane & 3) * 2;
    const int jg = ct * 8 + jm;
    const float* __restrict__ xp_t = g_xp + (size_t)t * B_ * G4_;
    __nv_bfloat16* __restrict__ hno = g_h_hi[(t + 1) & 1];
    __nv_bfloat16* __restrict__ lno = g_h_lo[(t + 1) & 1];

    #pragma unroll
    for (int rr = 0; rr < 2; rr++) {
        const int r = rr ? r1 : r0;
        const int ci = rr * 2;
        const float* __restrict__ xr = xp_t + (size_t)r * G4_ + ct * 32;
        float2 xg = *(const float2*)(xr + 0  + jm);
        float2 xi = *(const float2*)(xr + 8  + jm);
        float2 xf = *(const float2*)(xr + 16 + jm);
        float2 xo = *(const float2*)(xr + 24 + jm);
        float2 cv = *(const float2*)(g_c + (size_t)r * H_ + jg);

        float zg0 = acc[0][ci] + xg.x, zg1 = acc[0][ci + 1] + xg.y;
        float zi0 = acc[1][ci] + xi.x, zi1 = acc[1][ci + 1] + xi.y;
        float zf0 = acc[2][ci] + xf.x, zf1 = acc[2][ci + 1] + xf.y;
        float zo0 = acc[3][ci] + xo.x, zo1 = acc[3][ci + 1] + xo.y;

        float cn0 = tanh_fast(zg0) * sigf(zi0) + cv.x * sigf(zf0);
        float cn1 = tanh_fast(zg1) * sigf(zi1) + cv.y * sigf(zf1);
        float hv0 = tanh_fast(cn0) * sigf(zo0);
        float hv1 = tanh_fast(cn1) * sigf(zo1);

        *(float2*)(g_c + (size_t)r * H_ + jg) = make_float2(cn0, cn1);
        __nv_bfloat16 h0 = __float2bfloat16(hv0), h1 = __float2bfloat16(hv1);
        *(__nv_bfloat162*)(hno + (size_t)r * H_ + jg) = __nv_bfloat162(h0, h1);
        *(__nv_bfloat162*)(lno + (size_t)r * H_ + jg) =
            __nv_bfloat162(__float2bfloat16(hv0 - __bfloat162float(h0)),
                           __float2bfloat16(hv1 - __bfloat162float(h1)));
    }
}

// ---------------------------------------------------------------------------
// Phase 3: out[b][c] = h_T[b] @ W_ph + b_p
// ---------------------------------------------------------------------------
__global__ void proj_kernel(const float* __restrict__ Wp,
                            const float* __restrict__ bp,
                            float* __restrict__ out) {
    const int b   = blockIdx.x;
    const int tid = threadIdx.x;
    const __nv_bfloat16* __restrict__ hh = g_h_hi[0] + (size_t)b * H_;
    const __nv_bfloat16* __restrict__ hl = g_h_lo[0] + (size_t)b * H_;

    float acc[C_];
    #pragma unroll
    for (int cc = 0; cc < C_; cc++) acc[cc] = 0.f;
    for (int j = tid; j < H_; j += blockDim.x) {
        float hv = __bfloat162float(hh[j]) + __bfloat162float(hl[j]);
        #pragma unroll
        for (int cc = 0; cc < C_; cc++) acc[cc] += hv * Wp[(size_t)j * C_ + cc];
    }
    __shared__ float red[256];
    for (int cc = 0; cc < C_; cc++) {
        red[tid] = acc[cc];
        __syncthreads();
        for (int s = 128; s > 0; s >>= 1) {
            if (tid < s) red[tid] += red[tid + s];
            __syncthreads();
        }
        if (tid == 0) out[(size_t)b * C_ + cc] = red[0] + bp[cc];
        __syncthreads();
    }
}

// ---------------------------------------------------------------------------
extern "C" void kernel_launch(void* const* d_in, const int* in_sizes, int n_in,
                              void* d_out, int out_size) {
    const float* x = nullptr;
    Ptrs4 Wx{}; Ptrs4 Wh{}; Ptrs4 bb{};
    const float* Wp = nullptr;
    const float* bp = nullptr;
    int nx = 0, nh = 0, nb = 0;
    for (int i = 0; i < n_in; i++) {
        const int sz = in_sizes[i];
        const float* p = (const float*)d_in[i];
        if      (sz == B_ * T_ * D_) x = p;
        else if (sz == D_ * H_)      { if (nx < 4) Wx.p[nx++] = p; }
        else if (sz == H_ * H_)      { if (nh < 4) Wh.p[nh++] = p; }
        else if (sz == H_)           { if (nb < 4) bb.p[nb++] = p; }
        else if (sz == H_ * C_)      Wp = p;
        else if (sz == C_)           bp = p;
    }

    cudaFuncSetAttribute(lstm_step_mma,
                         cudaFuncAttributeMaxDynamicSharedMemorySize, S_SMEM);
    cudaFuncSetAttribute(xp_mma,
                         cudaFuncAttributeMaxDynamicSharedMemorySize, X_SMEM);

    init_state<<<(B_ * H_ + 255) / 256, 256>>>();
    repack_wh<<<H_, 256>>>(Wh);
    repack_wx<<<D_, 256>>>(Wx);
    repack_bias<<<(G4_ + 255) / 256, 256>>>(bb);
    xp_mma<<<dim3(G4_ / 64, T_), 256, X_SMEM>>>(x);
    for (int t = 0; t < T_; t++)
        lstm_step_mma<<<B_, 256, S_SMEM>>>(t);
    proj_kernel<<<B_, 256>>>(Wp, bp, (float*)d_out);
}